// round 5
// baseline (speedup 1.0000x reference)
#include <cuda_runtime.h>
#include <math.h>

#define LQ 8000
#define NC 512
#define BC 128
#define NBLK_ 24

// ---------------- device scratch (no allocation allowed) ----------------
__device__ float g_buf0[4 * BC * LQ];   // "out" activation
__device__ float g_buf1[4 * BC * LQ];   // "h" (conv output)
__device__ float g_wg[BC * NC];         // w_comp * gn_g
__device__ float g_wb[BC];              // sum w_comp * gn_b
__device__ float g_wgs[BC];             // sum wg
__device__ float g_pwg[NBLK_ * BC * BC];
__device__ float g_pwb[NBLK_ * BC];
__device__ float g_pwgs[NBLK_ * BC];
__device__ float g_part[4 * NC * 2];    // per-row partial (sum, sumsq)
__device__ float g_mean[4];
__device__ float g_rstd[4];

// ---------------- weight prep ----------------
__global__ void prep_wg_kernel(const float* __restrict__ w, const float* __restrict__ g,
                               const float* __restrict__ beta,
                               float* __restrict__ wg, float* __restrict__ wb,
                               float* __restrict__ wgs) {
    int o = threadIdx.x;  // 0..127
    float sb = 0.f, sg = 0.f;
    for (int n = 0; n < NC; n++) {
        float wv = w[o * NC + n];
        float v = wv * g[n];
        wg[o * NC + n] = v;
        sb += wv * beta[n];
        sg += v;
    }
    wb[o] = sb;
    wgs[o] = sg;
}

__global__ void prep_pwg_kernel(const float* __restrict__ pw, const float* __restrict__ tg,
                                const float* __restrict__ tb,
                                float* __restrict__ pwg, float* __restrict__ pwb,
                                float* __restrict__ pwgs) {
    int i = blockIdx.x;   // block index 0..23
    int o = threadIdx.x;  // 0..127
    float sb = 0.f, sg = 0.f;
    for (int c = 0; c < BC; c++) {
        float wv = pw[(size_t)(i * BC + o) * BC + c];
        float v = wv * tg[i * BC + c];
        pwg[(size_t)(i * BC + o) * BC + c] = v;
        sb += wv * tb[i * BC + c];
        sg += v;
    }
    pwb[i * BC + o] = sb;
    pwgs[i * BC + o] = sg;
}

// ---------------- per-row stats (deterministic) ----------------
__global__ void rowstats_kernel(const float* __restrict__ src, int C,
                                float* __restrict__ part) {
    int c = blockIdx.x, b = blockIdx.y;
    const float* row = src + ((size_t)b * C + c) * LQ;
    float s = 0.f, ss = 0.f;
    for (int l = threadIdx.x; l < LQ; l += 256) {
        float v = row[l];
        s += v;
        ss += v * v;
    }
    __shared__ float rs[256], rss[256];
    rs[threadIdx.x] = s; rss[threadIdx.x] = ss;
    __syncthreads();
    for (int off = 128; off > 0; off >>= 1) {
        if ((int)threadIdx.x < off) {
            rs[threadIdx.x] += rs[threadIdx.x + off];
            rss[threadIdx.x] += rss[threadIdx.x + off];
        }
        __syncthreads();
    }
    if (threadIdx.x == 0) {
        part[(b * C + c) * 2 + 0] = rs[0];
        part[(b * C + c) * 2 + 1] = rss[0];
    }
}

__global__ void finalize_kernel(const float* __restrict__ part, int C, float invCnt) {
    int b = blockIdx.x;
    int tid = threadIdx.x;
    float s = 0.f, ss = 0.f;
    for (int c = tid; c < C; c += 256) {
        s += part[(b * C + c) * 2 + 0];
        ss += part[(b * C + c) * 2 + 1];
    }
    __shared__ float rs[256], rss[256];
    rs[tid] = s; rss[tid] = ss;
    __syncthreads();
    for (int off = 128; off > 0; off >>= 1) {
        if (tid < off) { rs[tid] += rs[tid + off]; rss[tid] += rss[tid + off]; }
        __syncthreads();
    }
    if (tid == 0) {
        float m = rs[0] * invCnt;
        float var = rss[0] * invCnt - m * m;
        g_mean[b] = m;
        g_rstd[b] = rsqrtf(var + 1e-5f);
    }
}

// ---------------- depthwise dilated conv + PReLU + row-stats ----------------
__global__ void dwconv_kernel(const float* __restrict__ src, const float* __restrict__ dw,
                              const float* __restrict__ pra, int d,
                              float* __restrict__ dst, float* __restrict__ part) {
    int c = blockIdx.x, b = blockIdx.y;
    float w0 = dw[c * 3 + 0], w1 = dw[c * 3 + 1], w2 = dw[c * 3 + 2];
    float a = pra[c];
    const float* row = src + ((size_t)b * BC + c) * LQ;
    float* orow = dst + ((size_t)b * BC + c) * LQ;
    int d2 = d << 1;
    float s = 0.f, ss = 0.f;
    for (int l = threadIdx.x; l < LQ; l += 256) {
        float v = w2 * row[l];
        if (l >= d)  v += w1 * row[l - d];
        if (l >= d2) v += w0 * row[l - d2];
        v = v > 0.f ? v : a * v;  // PReLU
        orow[l] = v;
        s += v;
        ss += v * v;
    }
    __shared__ float rs[256], rss[256];
    rs[threadIdx.x] = s; rss[threadIdx.x] = ss;
    __syncthreads();
    for (int off = 128; off > 0; off >>= 1) {
        if ((int)threadIdx.x < off) {
            rs[threadIdx.x] += rs[threadIdx.x + off];
            rss[threadIdx.x] += rss[threadIdx.x + off];
        }
        __syncthreads();
    }
    if (threadIdx.x == 0) {
        part[(b * BC + c) * 2 + 0] = rs[0];
        part[(b * BC + c) * 2 + 1] = rss[0];
    }
}

// ---------------- fused GN + 1x1 GEMM (+residual / +sigmoid) ----------------
// Y[b,o,l] = act( alpha * dot(W[o,:], X[b,:,l]) + bias[b,o] (+ Y[b,o,l]) )
// STATS: alpha = rstd[b], bias = ba[o] - mean[b]*rstd[b]*bb[o]
// Tile: 128 M x 64 L per block, KT = 128, 256 threads, 4x8 per-thread tile.
template <bool STATS, bool RES, bool SIG>
__global__ void __launch_bounds__(256)
gemm_kernel(const float* __restrict__ W, const float* __restrict__ X,
            float* __restrict__ Y,
            const float* __restrict__ ba, const float* __restrict__ bb,
            int K, int Mtotal) {
    extern __shared__ float smem[];
    float* sw = smem;            // [128 kk][128 m]  (k-major -> conflict-free LDS.128)
    float* sh = smem + 16384;    // [128 kk][64 l]
    const int tid = threadIdx.x;
    const int tr = tid & 31;     // m4 index 0..31  (m = 4*tr..4*tr+3)
    const int tc = tid >> 5;     // 0..7            (l = 8*tc..8*tc+7)
    const int b = blockIdx.z;
    const int m0 = blockIdx.y << 7;
    const int l0 = blockIdx.x << 6;
    const float* Xb = X + ((size_t)b * K) * LQ + l0;
    const float* Wb = W + (size_t)m0 * K;

    float acc[4][8];
#pragma unroll
    for (int j = 0; j < 4; j++)
#pragma unroll
        for (int jj = 0; jj < 8; jj++) acc[j][jj] = 0.f;

    const int nchunk = K >> 7;
    for (int ch = 0; ch < nchunk; ch++) {
        const int k0 = ch << 7;
        // W chunk: global coalesced scalar reads (k fastest), store k-major.
#pragma unroll 8
        for (int it = 0; it < 64; it++) {
            int idx = tid + (it << 8);
            int k = idx & 127, m = idx >> 7;
            sw[(k << 7) + m] = Wb[(size_t)m * K + k0 + k];
        }
        // X chunk: float4 coalesced, row-major [kk][64]
#pragma unroll
        for (int it = 0; it < 8; it++) {
            int idx = tid + (it << 8);
            int row = idx >> 4, c4 = idx & 15;
            float4 v = *(const float4*)(Xb + (size_t)(k0 + row) * LQ + (c4 << 2));
            *(float4*)(sh + (row << 6) + (c4 << 2)) = v;
        }
        __syncthreads();
        const float4* sw4 = (const float4*)sw;
        const float4* sh4 = (const float4*)sh;
#pragma unroll 4
        for (int kk = 0; kk < 128; kk++) {
            float4 wv = sw4[(kk << 5) + tr];
            float4 x0 = sh4[(kk << 4) + (tc << 1)];
            float4 x1 = sh4[(kk << 4) + (tc << 1) + 1];
            float ws[4] = {wv.x, wv.y, wv.z, wv.w};
            float xs[8] = {x0.x, x0.y, x0.z, x0.w, x1.x, x1.y, x1.z, x1.w};
#pragma unroll
            for (int j = 0; j < 4; j++)
#pragma unroll
                for (int jj = 0; jj < 8; jj++)
                    acc[j][jj] = fmaf(ws[j], xs[jj], acc[j][jj]);
        }
        __syncthreads();
    }

    float mval = 0.f, rval = 1.f;
    if (STATS) { mval = g_mean[b]; rval = g_rstd[b]; }
#pragma unroll
    for (int j = 0; j < 4; j++) {
        int o = m0 + (tr << 2) + j;
        float bias = 0.f;
        if (STATS) bias = ba[o] - mval * rval * bb[o];
        float* yp = Y + ((size_t)b * Mtotal + o) * LQ + l0 + (tc << 3);
#pragma unroll
        for (int h4 = 0; h4 < 2; h4++) {
            float4 v4;
            float* vv = (float*)&v4;
#pragma unroll
            for (int q = 0; q < 4; q++) {
                float v = acc[j][h4 * 4 + q];
                if (STATS) v = rval * v + bias;
                vv[q] = v;
            }
            if (RES) {
                float4 r4 = *(const float4*)(yp + h4 * 4);
                v4.x += r4.x; v4.y += r4.y; v4.z += r4.z; v4.w += r4.w;
            }
            if (SIG) {
                v4.x = 1.f / (1.f + expf(-v4.x));
                v4.y = 1.f / (1.f + expf(-v4.y));
                v4.z = 1.f / (1.f + expf(-v4.z));
                v4.w = 1.f / (1.f + expf(-v4.w));
            }
            *(float4*)(yp + h4 * 4) = v4;
        }
    }
}

// ---------------- launch ----------------
extern "C" void kernel_launch(void* const* d_in, const int* in_sizes, int n_in,
                              void* d_out, int out_size) {
    const float* x      = (const float*)d_in[0];
    const float* gn_g   = (const float*)d_in[1];
    const float* gn_b   = (const float*)d_in[2];
    const float* w_comp = (const float*)d_in[3];
    const float* dw_w   = (const float*)d_in[4];
    const float* pr_a   = (const float*)d_in[5];
    const float* tn_g   = (const float*)d_in[6];
    const float* tn_b   = (const float*)d_in[7];
    const float* pw_w   = (const float*)d_in[8];
    const float* w_exp  = (const float*)d_in[9];
    float* out = (float*)d_out;

    float *p_buf0, *p_buf1, *p_wg, *p_wb, *p_wgs, *p_pwg, *p_pwb, *p_pwgs, *p_part;
    cudaGetSymbolAddress((void**)&p_buf0, g_buf0);
    cudaGetSymbolAddress((void**)&p_buf1, g_buf1);
    cudaGetSymbolAddress((void**)&p_wg,   g_wg);
    cudaGetSymbolAddress((void**)&p_wb,   g_wb);
    cudaGetSymbolAddress((void**)&p_wgs,  g_wgs);
    cudaGetSymbolAddress((void**)&p_pwg,  g_pwg);
    cudaGetSymbolAddress((void**)&p_pwb,  g_pwb);
    cudaGetSymbolAddress((void**)&p_pwgs, g_pwgs);
    cudaGetSymbolAddress((void**)&p_part, g_part);

    const int SMEM = (16384 + 8192) * 4;  // 96 KB dynamic
    cudaFuncSetAttribute(gemm_kernel<true, false, false>,
                         cudaFuncAttributeMaxDynamicSharedMemorySize, SMEM);
    cudaFuncSetAttribute(gemm_kernel<true, true, false>,
                         cudaFuncAttributeMaxDynamicSharedMemorySize, SMEM);
    cudaFuncSetAttribute(gemm_kernel<false, false, true>,
                         cudaFuncAttributeMaxDynamicSharedMemorySize, SMEM);

    // weight folding
    prep_wg_kernel<<<1, 128>>>(w_comp, gn_g, gn_b, p_wg, p_wb, p_wgs);
    prep_pwg_kernel<<<NBLK_, 128>>>(pw_w, tn_g, tn_b, p_pwg, p_pwb, p_pwgs);

    // outer GroupNorm stats on x
    rowstats_kernel<<<dim3(NC, 4), 256>>>(x, NC, p_part);
    finalize_kernel<<<4, 256>>>(p_part, NC, 1.f / ((float)NC * (float)LQ));

    // GN-fused compression GEMM: x[4,512,8000] -> buf0[4,128,8000]
    gemm_kernel<true, false, false><<<dim3(125, 1, 4), 256, SMEM>>>(
        p_wg, x, p_buf0, p_wb, p_wgs, NC, BC);

    // 24 TCN blocks
    for (int i = 0; i < NBLK_; i++) {
        int d = 1 << (i & 7);
        dwconv_kernel<<<dim3(BC, 4), 256>>>(p_buf0, dw_w + i * BC * 3,
                                            pr_a + i * BC, d, p_buf1, p_part);
        finalize_kernel<<<4, 256>>>(p_part, BC, 1.f / ((float)BC * (float)LQ));
        gemm_kernel<true, true, false><<<dim3(125, 1, 4), 256, SMEM>>>(
            p_pwg + (size_t)i * BC * BC, p_buf1, p_buf0,
            p_pwb + i * BC, p_pwgs + i * BC, BC, BC);
    }

    // expansion GEMM + sigmoid: buf0[4,128,8000] -> out[4,1024,8000]
    gemm_kernel<false, false, true><<<dim3(125, 8, 4), 256, SMEM>>>(
        w_exp, p_buf0, out, nullptr, nullptr, BC, 1024);
}

// round 6
// speedup vs baseline: 1.8409x; 1.8409x over previous
#include <cuda_runtime.h>
#include <math.h>
#include <stdint.h>

#define LQ 8000
#define LP 8064          // padded length for scratch activations (63*128)
#define NC 512
#define BC 128
#define NBLK_ 24

// ---------------- device scratch (zero-initialized at module load) ----------------
__device__ float g_buf0[4 * BC * LP];     // "out" activation (padded)
__device__ float g_buf1[4 * BC * LP];     // "h" conv output (padded; pads stay 0)
__device__ float g_wgT[NC * BC];          // (w_comp*gn_g)^T   [n][o]
__device__ float g_wb[BC];                // sum_n w_comp*gn_b
__device__ float g_wgs[BC];               // sum_n w_comp*gn_g
__device__ float g_pwgT[NBLK_ * BC * BC]; // (pw*tn_g)^T per block [i][c][o]
__device__ float g_pwb[NBLK_ * BC];
__device__ float g_pwgs[NBLK_ * BC];
__device__ float g_wexpT[BC * 1024];      // w_exp^T [c][o]
__device__ float g_part[4 * NC * 2];      // per-row partial (sum, sumsq)

// ---------------- weight prep ----------------
__global__ void transpose_wg_kernel(const float* __restrict__ w, const float* __restrict__ g,
                                    float* __restrict__ wgT) {
    int idx = blockIdx.x * 256 + threadIdx.x;      // 512*128 = 65536
    if (idx >= NC * BC) return;
    int n = idx >> 7, o = idx & 127;
    wgT[idx] = w[o * NC + n] * g[n];
}

__global__ void sums_wg_kernel(const float* __restrict__ w, const float* __restrict__ g,
                               const float* __restrict__ beta,
                               float* __restrict__ wb, float* __restrict__ wgs) {
    int o = threadIdx.x;
    float sb = 0.f, sg = 0.f;
    for (int n = 0; n < NC; n++) {
        float wv = w[o * NC + n];
        sb += wv * beta[n];
        sg += wv * g[n];
    }
    wb[o] = sb;
    wgs[o] = sg;
}

__global__ void transpose_pw_kernel(const float* __restrict__ pw, const float* __restrict__ tg,
                                    float* __restrict__ pwT) {
    int i = blockIdx.y;
    int idx = blockIdx.x * 256 + threadIdx.x;      // 16384 per block i
    if (idx >= BC * BC) return;
    int c = idx >> 7, o = idx & 127;
    pwT[i * BC * BC + idx] = pw[(size_t)i * BC * BC + o * BC + c] * tg[i * BC + c];
}

__global__ void sums_pw_kernel(const float* __restrict__ pw, const float* __restrict__ tg,
                               const float* __restrict__ tb,
                               float* __restrict__ pwb, float* __restrict__ pwgs) {
    int i = blockIdx.x, o = threadIdx.x;
    float sb = 0.f, sg = 0.f;
    for (int c = 0; c < BC; c++) {
        float wv = pw[(size_t)(i * BC + o) * BC + c];
        sb += wv * tb[i * BC + c];
        sg += wv * tg[i * BC + c];
    }
    pwb[i * BC + o] = sb;
    pwgs[i * BC + o] = sg;
}

__global__ void transpose_wexp_kernel(const float* __restrict__ w, float* __restrict__ wT) {
    int idx = blockIdx.x * 256 + threadIdx.x;      // 131072
    if (idx >= BC * 1024) return;
    int c = idx >> 10, o = idx & 1023;
    wT[idx] = w[o * BC + c];
}

// ---------------- per-row stats of x (deterministic) ----------------
__global__ void rowstats_kernel(const float* __restrict__ src, float* __restrict__ part) {
    int c = blockIdx.x, b = blockIdx.y;
    const float4* row = (const float4*)(src + ((size_t)b * NC + c) * LQ);
    float s = 0.f, ss = 0.f;
    for (int i = threadIdx.x; i < LQ / 4; i += 256) {
        float4 v = row[i];
        s += v.x + v.y + v.z + v.w;
        ss += v.x * v.x + v.y * v.y + v.z * v.z + v.w * v.w;
    }
    __shared__ float rs[256], rss[256];
    rs[threadIdx.x] = s; rss[threadIdx.x] = ss;
    __syncthreads();
    for (int off = 128; off > 0; off >>= 1) {
        if ((int)threadIdx.x < off) {
            rs[threadIdx.x] += rs[threadIdx.x + off];
            rss[threadIdx.x] += rss[threadIdx.x + off];
        }
        __syncthreads();
    }
    if (threadIdx.x == 0) {
        part[(b * NC + c) * 2 + 0] = rs[0];
        part[(b * NC + c) * 2 + 1] = rss[0];
    }
}

// ---------------- depthwise dilated conv + PReLU + row-stats ----------------
__global__ void __launch_bounds__(256) dwconv_kernel(
    const float* __restrict__ src, const float* __restrict__ dw,
    const float* __restrict__ pra, int d,
    float* __restrict__ dst, float* __restrict__ part) {
    __shared__ float srow[LQ];
    __shared__ float rs[256], rss[256];
    int c = blockIdx.x, b = blockIdx.y;
    int tid = threadIdx.x;
    const float4* row = (const float4*)(src + ((size_t)b * BC + c) * LP);
    float4* orow = (float4*)(dst + ((size_t)b * BC + c) * LP);
    for (int i = tid; i < LQ / 4; i += 256) ((float4*)srow)[i] = row[i];
    __syncthreads();
    float w0 = dw[c * 3 + 0], w1 = dw[c * 3 + 1], w2 = dw[c * 3 + 2];
    float a = pra[c];
    int d2 = d << 1;
    float s = 0.f, ss = 0.f;
    for (int i = tid; i < LQ / 4; i += 256) {
        int l = i << 2;
        float4 o;
        float* op = (float*)&o;
#pragma unroll
        for (int j = 0; j < 4; j++) {
            int ll = l + j;
            float v = w2 * srow[ll];
            if (ll >= d)  v += w1 * srow[ll - d];
            if (ll >= d2) v += w0 * srow[ll - d2];
            v = v > 0.f ? v : a * v;
            op[j] = v;
            s += v;
            ss += v * v;
        }
        orow[i] = o;
    }
    rs[tid] = s; rss[tid] = ss;
    __syncthreads();
    for (int off = 128; off > 0; off >>= 1) {
        if (tid < off) { rs[tid] += rs[tid + off]; rss[tid] += rss[tid + off]; }
        __syncthreads();
    }
    if (tid == 0) {
        part[(b * BC + c) * 2 + 0] = rs[0];
        part[(b * BC + c) * 2 + 1] = rss[0];
    }
}

// ---------------- fused GN + 1x1 GEMM via packed f32x2 FMA ----------------
// Y[b,o,l] = act( rstd * dot(WT[:,o], X[b,:,l]) + bias[b,o] (+ Y[b,o,l]) )
// M-tile = 128, L-tile = LT, K chunked by 64 with 2-stage cp.async pipeline.
// 256 threads: tl = tid&15 (NL=LT/16 l's each), tm = tid>>4 (8 m's each).
// Accumulators pair adjacent m's in one 64-bit f32x2 register.
template <int KTOT, int LT, bool STATS, bool RES, bool SIG, bool MASK>
__global__ void __launch_bounds__(256) gemm2_kernel(
    const float* __restrict__ WT,   // [KTOT][Mtotal] k-major
    const float* __restrict__ X, int xstride,
    float* __restrict__ Y, int ystride, int Mtotal,
    const float* __restrict__ ba, const float* __restrict__ bb,
    const float* __restrict__ part, int C, float invCnt) {
    constexpr int NL = LT / 16;
    constexpr int NCH = KTOT / 64;
    extern __shared__ float sm[];
    float* sW = sm;                       // [2][64][128]
    float* sX = sm + 2 * 64 * 128;        // [2][64][LT]
    __shared__ float sS[256], sS2[256];
    __shared__ float sMean, sRstd;

    const int tid = threadIdx.x;
    const int tl = tid & 15, tm = tid >> 4;
    const int b = blockIdx.z;
    const int l0 = blockIdx.x * LT;
    const int m0 = blockIdx.y << 7;
    const float* Wg = WT + m0;
    const float* Xg = X + (size_t)b * KTOT * xstride + l0;

    auto load_chunk = [&](int kc, int bufi) {
        float* dW = sW + bufi * 64 * 128;
        const float* srcW = Wg + (size_t)kc * 64 * Mtotal;
#pragma unroll
        for (int it = 0; it < 8; it++) {
            int idx = tid + (it << 8);          // float4 idx in [64][32]
            int r = idx >> 5, c4 = idx & 31;
            uint32_t dst = (uint32_t)__cvta_generic_to_shared(dW + (r << 7) + (c4 << 2));
            const float* srcp = srcW + (size_t)r * Mtotal + (c4 << 2);
            asm volatile("cp.async.cg.shared.global [%0], [%1], 16;" :: "r"(dst), "l"(srcp));
        }
        float* dX = sX + bufi * 64 * LT;
        const float* srcX = Xg + (size_t)kc * 64 * xstride;
#pragma unroll
        for (int it = 0; it < NL; it++) {       // 64*LT/4/256 float4s
            int idx = tid + (it << 8);
            int r = idx / (LT / 4), c4 = idx % (LT / 4);
            uint32_t dst = (uint32_t)__cvta_generic_to_shared(dX + r * LT + (c4 << 2));
            const float* srcp = srcX + (size_t)r * xstride + (c4 << 2);
            asm volatile("cp.async.cg.shared.global [%0], [%1], 16;" :: "r"(dst), "l"(srcp));
        }
        asm volatile("cp.async.commit_group;");
    };

    load_chunk(0, 0);

    if (STATS) {   // inline deterministic finalize of per-row partials
        float s = 0.f, ss = 0.f;
        for (int c = tid; c < C; c += 256) {
            s += part[(b * C + c) * 2 + 0];
            ss += part[(b * C + c) * 2 + 1];
        }
        sS[tid] = s; sS2[tid] = ss;
        __syncthreads();
        for (int off = 128; off > 0; off >>= 1) {
            if (tid < off) { sS[tid] += sS[tid + off]; sS2[tid] += sS2[tid + off]; }
            __syncthreads();
        }
        if (tid == 0) {
            float m = sS[0] * invCnt;
            float v = sS2[0] * invCnt - m * m;
            sMean = m;
            sRstd = rsqrtf(v + 1e-5f);
        }
        __syncthreads();
    }

    unsigned long long acc[4][NL];
#pragma unroll
    for (int mp = 0; mp < 4; mp++)
#pragma unroll
        for (int j = 0; j < NL; j++) acc[mp][j] = 0ull;

    int buf = 0;
    for (int kc = 0; kc < NCH; kc++) {
        if (kc + 1 < NCH) {
            load_chunk(kc + 1, buf ^ 1);
            asm volatile("cp.async.wait_group 1;");
        } else {
            asm volatile("cp.async.wait_group 0;");
        }
        __syncthreads();
        const float* wr = sW + buf * 64 * 128 + (tm << 3);
        const float* xr = sX + buf * 64 * LT + tl * NL;
#pragma unroll 4
        for (int kk = 0; kk < 64; kk++) {
            ulonglong2 wp01 = *(const ulonglong2*)(wr + (kk << 7));
            ulonglong2 wp23 = *(const ulonglong2*)(wr + (kk << 7) + 4);
            unsigned long long wp[4] = {wp01.x, wp01.y, wp23.x, wp23.y};
            float xv[NL];
            *(float4*)xv = *(const float4*)(xr + kk * LT);
            if (NL == 8) *(float4*)(xv + 4) = *(const float4*)(xr + kk * LT + 4);
            unsigned long long xp[NL];
#pragma unroll
            for (int j = 0; j < NL; j++) {
                uint32_t u = __float_as_uint(xv[j]);
                asm("mov.b64 %0, {%1, %1};" : "=l"(xp[j]) : "r"(u));
            }
#pragma unroll
            for (int mp = 0; mp < 4; mp++)
#pragma unroll
                for (int j = 0; j < NL; j++)
                    asm("fma.rn.f32x2 %0, %1, %2, %0;"
                        : "+l"(acc[mp][j]) : "l"(wp[mp]), "l"(xp[j]));
        }
        __syncthreads();
        buf ^= 1;
    }

    float mean = 0.f, rstd = 1.f;
    if (STATS) { mean = sMean; rstd = sRstd; }
    const int lbase = l0 + tl * NL;
#pragma unroll
    for (int mp = 0; mp < 4; mp++) {
#pragma unroll
        for (int half = 0; half < 2; half++) {
            int o = m0 + (tm << 3) + 2 * mp + half;
            float bias = 0.f;
            if (STATS) bias = ba[o] - mean * rstd * bb[o];
            float* yp = Y + ((size_t)b * Mtotal + o) * ystride + lbase;
            float vals[NL];
#pragma unroll
            for (int j = 0; j < NL; j++) {
                unsigned long long u = acc[mp][j];
                uint32_t w = half ? (uint32_t)(u >> 32) : (uint32_t)u;
                float v = __uint_as_float(w);
                if (STATS) v = fmaf(rstd, v, bias);
                vals[j] = v;
            }
#pragma unroll
            for (int g4 = 0; g4 < NL / 4; g4++) {
                if (MASK && (lbase + (g4 << 2)) >= LQ) continue;
                float4 v4 = *(float4*)(vals + (g4 << 2));
                if (RES) {
                    float4 r = *(const float4*)(yp + (g4 << 2));
                    v4.x += r.x; v4.y += r.y; v4.z += r.z; v4.w += r.w;
                }
                if (SIG) {
                    v4.x = 1.f / (1.f + expf(-v4.x));
                    v4.y = 1.f / (1.f + expf(-v4.y));
                    v4.z = 1.f / (1.f + expf(-v4.z));
                    v4.w = 1.f / (1.f + expf(-v4.w));
                }
                *(float4*)(yp + (g4 << 2)) = v4;
            }
        }
    }
}

// ---------------- launch ----------------
extern "C" void kernel_launch(void* const* d_in, const int* in_sizes, int n_in,
                              void* d_out, int out_size) {
    const float* x      = (const float*)d_in[0];
    const float* gn_g   = (const float*)d_in[1];
    const float* gn_b   = (const float*)d_in[2];
    const float* w_comp = (const float*)d_in[3];
    const float* dw_w   = (const float*)d_in[4];
    const float* pr_a   = (const float*)d_in[5];
    const float* tn_g   = (const float*)d_in[6];
    const float* tn_b   = (const float*)d_in[7];
    const float* pw_w   = (const float*)d_in[8];
    const float* w_exp  = (const float*)d_in[9];
    float* out = (float*)d_out;

    float *p_buf0, *p_buf1, *p_wgT, *p_wb, *p_wgs, *p_pwgT, *p_pwb, *p_pwgs,
          *p_wexpT, *p_part;
    cudaGetSymbolAddress((void**)&p_buf0,  g_buf0);
    cudaGetSymbolAddress((void**)&p_buf1,  g_buf1);
    cudaGetSymbolAddress((void**)&p_wgT,   g_wgT);
    cudaGetSymbolAddress((void**)&p_wb,    g_wb);
    cudaGetSymbolAddress((void**)&p_wgs,   g_wgs);
    cudaGetSymbolAddress((void**)&p_pwgT,  g_pwgT);
    cudaGetSymbolAddress((void**)&p_pwb,   g_pwb);
    cudaGetSymbolAddress((void**)&p_pwgs,  g_pwgs);
    cudaGetSymbolAddress((void**)&p_wexpT, g_wexpT);
    cudaGetSymbolAddress((void**)&p_part,  g_part);

    const int SM64  = (2 * 64 * 128 + 2 * 64 * 64) * 4;   // 96 KB
    const int SM128 = (2 * 64 * 128 + 2 * 64 * 128) * 4;  // 128 KB
    cudaFuncSetAttribute(gemm2_kernel<512, 64, true, false, false, false>,
                         cudaFuncAttributeMaxDynamicSharedMemorySize, SM64);
    cudaFuncSetAttribute(gemm2_kernel<128, 128, true, true, false, false>,
                         cudaFuncAttributeMaxDynamicSharedMemorySize, SM128);
    cudaFuncSetAttribute(gemm2_kernel<128, 128, false, false, true, true>,
                         cudaFuncAttributeMaxDynamicSharedMemorySize, SM128);

    // ---- weight prep (tiny) ----
    transpose_wg_kernel<<<(NC * BC + 255) / 256, 256>>>(w_comp, gn_g, p_wgT);
    sums_wg_kernel<<<1, 128>>>(w_comp, gn_g, gn_b, p_wb, p_wgs);
    transpose_pw_kernel<<<dim3((BC * BC + 255) / 256, NBLK_), 256>>>(pw_w, tn_g, p_pwgT);
    sums_pw_kernel<<<NBLK_, 128>>>(pw_w, tn_g, tn_b, p_pwb, p_pwgs);
    transpose_wexp_kernel<<<(BC * 1024 + 255) / 256, 256>>>(w_exp, p_wexpT);

    // ---- outer GroupNorm stats on x ----
    rowstats_kernel<<<dim3(NC, 4), 256>>>(x, p_part);

    // ---- GN-fused compression GEMM: x[4,512,8000] -> buf0[4,128,8064-padded] ----
    gemm2_kernel<512, 64, true, false, false, false><<<dim3(125, 1, 4), 256, SM64>>>(
        p_wgT, x, LQ, p_buf0, LP, BC, p_wb, p_wgs, p_part, NC,
        1.f / ((float)NC * (float)LQ));

    // ---- 24 TCN blocks ----
    for (int i = 0; i < NBLK_; i++) {
        int d = 1 << (i & 7);
        dwconv_kernel<<<dim3(BC, 4), 256>>>(p_buf0, dw_w + i * BC * 3,
                                            pr_a + i * BC, d, p_buf1, p_part);
        gemm2_kernel<128, 128, true, true, false, false><<<dim3(63, 1, 4), 256, SM128>>>(
            p_pwgT + (size_t)i * BC * BC, p_buf1, LP, p_buf0, LP, BC,
            p_pwb + i * BC, p_pwgs + i * BC, p_part, BC,
            1.f / ((float)BC * (float)LQ));
    }

    // ---- expansion GEMM + sigmoid: buf0 -> out[4,1024,8000] (masked stores) ----
    gemm2_kernel<128, 128, false, false, true, true><<<dim3(63, 8, 4), 256, SM128>>>(
        p_wexpT, p_buf0, LP, out, LQ, 1024, nullptr, nullptr, nullptr, 0, 0.f);
}

// round 7
// speedup vs baseline: 1.8472x; 1.0034x over previous
#include <cuda_runtime.h>
#include <math.h>
#include <stdint.h>

#define LQ 8000
#define LP 8064          // padded length for scratch activations (63*128)
#define NC 512
#define BC 128
#define NBLK_ 24

// ---------------- device scratch (zero-initialized at module load) ----------------
__device__ float g_buf0[4 * BC * LP];     // "out" activation (padded)
__device__ float g_buf1[4 * BC * LP];     // "h" conv output (padded; pads stay 0)
__device__ float g_wgT[NC * BC];          // (w_comp*gn_g)^T   [n][o]
__device__ float g_wb[BC];                // sum_n w_comp*gn_b
__device__ float g_wgs[BC];               // sum_n w_comp*gn_g
__device__ float g_pwgT[NBLK_ * BC * BC]; // (pw*tn_g)^T per block [i][c][o]
__device__ float g_pwb[NBLK_ * BC];
__device__ float g_pwgs[NBLK_ * BC];
__device__ float g_wexpT[BC * 1024];      // w_exp^T [c][o]
__device__ float g_part[4 * NC * 2];      // per-row partial (sum, sumsq)

// ---------------- weight prep ----------------
__global__ void transpose_wg_kernel(const float* __restrict__ w, const float* __restrict__ g,
                                    float* __restrict__ wgT) {
    int idx = blockIdx.x * 256 + threadIdx.x;      // 512*128 = 65536
    if (idx >= NC * BC) return;
    int n = idx >> 7, o = idx & 127;
    wgT[idx] = w[o * NC + n] * g[n];
}

__global__ void sums_wg_kernel(const float* __restrict__ w, const float* __restrict__ g,
                               const float* __restrict__ beta,
                               float* __restrict__ wb, float* __restrict__ wgs) {
    int o = threadIdx.x;
    float sb = 0.f, sg = 0.f;
    for (int n = 0; n < NC; n++) {
        float wv = w[o * NC + n];
        sb += wv * beta[n];
        sg += wv * g[n];
    }
    wb[o] = sb;
    wgs[o] = sg;
}

__global__ void transpose_pw_kernel(const float* __restrict__ pw, const float* __restrict__ tg,
                                    float* __restrict__ pwT) {
    int i = blockIdx.y;
    int idx = blockIdx.x * 256 + threadIdx.x;      // 16384 per block i
    if (idx >= BC * BC) return;
    int c = idx >> 7, o = idx & 127;
    pwT[i * BC * BC + idx] = pw[(size_t)i * BC * BC + o * BC + c] * tg[i * BC + c];
}

__global__ void sums_pw_kernel(const float* __restrict__ pw, const float* __restrict__ tg,
                               const float* __restrict__ tb,
                               float* __restrict__ pwb, float* __restrict__ pwgs) {
    int i = blockIdx.x, o = threadIdx.x;
    float sb = 0.f, sg = 0.f;
    for (int c = 0; c < BC; c++) {
        float wv = pw[(size_t)(i * BC + o) * BC + c];
        sb += wv * tb[i * BC + c];
        sg += wv * tg[i * BC + c];
    }
    pwb[i * BC + o] = sb;
    pwgs[i * BC + o] = sg;
}

__global__ void transpose_wexp_kernel(const float* __restrict__ w, float* __restrict__ wT) {
    int idx = blockIdx.x * 256 + threadIdx.x;      // 131072
    if (idx >= BC * 1024) return;
    int c = idx >> 10, o = idx & 1023;
    wT[idx] = w[o * BC + c];
}

// ---------------- per-row stats of x (deterministic) ----------------
__global__ void rowstats_kernel(const float* __restrict__ src, float* __restrict__ part) {
    int c = blockIdx.x, b = blockIdx.y;
    const float4* row = (const float4*)(src + ((size_t)b * NC + c) * LQ);
    float s = 0.f, ss = 0.f;
    for (int i = threadIdx.x; i < LQ / 4; i += 256) {
        float4 v = row[i];
        s += v.x + v.y + v.z + v.w;
        ss += v.x * v.x + v.y * v.y + v.z * v.z + v.w * v.w;
    }
    __shared__ float rs[256], rss[256];
    rs[threadIdx.x] = s; rss[threadIdx.x] = ss;
    __syncthreads();
    for (int off = 128; off > 0; off >>= 1) {
        if ((int)threadIdx.x < off) {
            rs[threadIdx.x] += rs[threadIdx.x + off];
            rss[threadIdx.x] += rss[threadIdx.x + off];
        }
        __syncthreads();
    }
    if (threadIdx.x == 0) {
        part[(b * NC + c) * 2 + 0] = rs[0];
        part[(b * NC + c) * 2 + 1] = rss[0];
    }
}

// ---------------- depthwise dilated conv + PReLU + row-stats ----------------
__global__ void __launch_bounds__(256) dwconv_kernel(
    const float* __restrict__ src, const float* __restrict__ dw,
    const float* __restrict__ pra, int d,
    float* __restrict__ dst, float* __restrict__ part) {
    __shared__ float srow[LQ];
    __shared__ float rs[256], rss[256];
    int c = blockIdx.x, b = blockIdx.y;
    int tid = threadIdx.x;
    const float4* row = (const float4*)(src + ((size_t)b * BC + c) * LP);
    float4* orow = (float4*)(dst + ((size_t)b * BC + c) * LP);
    for (int i = tid; i < LQ / 4; i += 256) ((float4*)srow)[i] = row[i];
    __syncthreads();
    float w0 = dw[c * 3 + 0], w1 = dw[c * 3 + 1], w2 = dw[c * 3 + 2];
    float a = pra[c];
    int d2 = d << 1;
    float s = 0.f, ss = 0.f;
    for (int i = tid; i < LQ / 4; i += 256) {
        int l = i << 2;
        float4 o;
        float* op = (float*)&o;
#pragma unroll
        for (int j = 0; j < 4; j++) {
            int ll = l + j;
            float v = w2 * srow[ll];
            if (ll >= d)  v += w1 * srow[ll - d];
            if (ll >= d2) v += w0 * srow[ll - d2];
            v = v > 0.f ? v : a * v;
            op[j] = v;
            s += v;
            ss += v * v;
        }
        orow[i] = o;
    }
    rs[tid] = s; rss[tid] = ss;
    __syncthreads();
    for (int off = 128; off > 0; off >>= 1) {
        if (tid < off) { rs[tid] += rs[tid + off]; rss[tid] += rss[tid + off]; }
        __syncthreads();
    }
    if (tid == 0) {
        part[(b * BC + c) * 2 + 0] = rs[0];
        part[(b * BC + c) * 2 + 1] = rss[0];
    }
}

// ---------------- fused GN + 1x1 GEMM via packed f32x2 FMA ----------------
// Y[b,o,l] = act( rstd * dot(WT[:,o], X[b,:,l]) + bias[b,o] (+ Y[b,o,l]) )
// M-tile = 128, L-tile = LT, K chunked by 64 with 2-stage cp.async pipeline.
// 256 threads: tl = tid&15 (NL=LT/16 l's each), tm = tid>>4 (8 m's each).
// Accumulators pair adjacent m's in one 64-bit f32x2 register.
template <int KTOT, int LT, bool STATS, bool RES, bool SIG, bool MASK>
__global__ void __launch_bounds__(256) gemm2_kernel(
    const float* __restrict__ WT,   // [KTOT][Mtotal] k-major
    const float* __restrict__ X, int xstride,
    float* __restrict__ Y, int ystride, int Mtotal,
    const float* __restrict__ ba, const float* __restrict__ bb,
    const float* __restrict__ part, int C, float invCnt) {
    constexpr int NL = LT / 16;
    constexpr int NCH = KTOT / 64;
    extern __shared__ float sm[];
    float* sW = sm;                       // [2][64][128]
    float* sX = sm + 2 * 64 * 128;        // [2][64][LT]
    __shared__ float sS[256], sS2[256];
    __shared__ float sMean, sRstd;

    const int tid = threadIdx.x;
    const int tl = tid & 15, tm = tid >> 4;
    const int b = blockIdx.z;
    const int l0 = blockIdx.x * LT;
    const int m0 = blockIdx.y << 7;
    const float* Wg = WT + m0;
    const float* Xg = X + (size_t)b * KTOT * xstride + l0;

    auto load_chunk = [&](int kc, int bufi) {
        float* dW = sW + bufi * 64 * 128;
        const float* srcW = Wg + (size_t)kc * 64 * Mtotal;
#pragma unroll
        for (int it = 0; it < 8; it++) {
            int idx = tid + (it << 8);          // float4 idx in [64][32]
            int r = idx >> 5, c4 = idx & 31;
            uint32_t dst = (uint32_t)__cvta_generic_to_shared(dW + (r << 7) + (c4 << 2));
            const float* srcp = srcW + (size_t)r * Mtotal + (c4 << 2);
            asm volatile("cp.async.cg.shared.global [%0], [%1], 16;" :: "r"(dst), "l"(srcp));
        }
        float* dX = sX + bufi * 64 * LT;
        const float* srcX = Xg + (size_t)kc * 64 * xstride;
#pragma unroll
        for (int it = 0; it < NL; it++) {       // 64*LT/4/256 float4s
            int idx = tid + (it << 8);
            int r = idx / (LT / 4), c4 = idx % (LT / 4);
            uint32_t dst = (uint32_t)__cvta_generic_to_shared(dX + r * LT + (c4 << 2));
            const float* srcp = srcX + (size_t)r * xstride + (c4 << 2);
            asm volatile("cp.async.cg.shared.global [%0], [%1], 16;" :: "r"(dst), "l"(srcp));
        }
        asm volatile("cp.async.commit_group;");
    };

    load_chunk(0, 0);

    if (STATS) {   // inline deterministic finalize of per-row partials
        float s = 0.f, ss = 0.f;
        for (int c = tid; c < C; c += 256) {
            s += part[(b * C + c) * 2 + 0];
            ss += part[(b * C + c) * 2 + 1];
        }
        sS[tid] = s; sS2[tid] = ss;
        __syncthreads();
        for (int off = 128; off > 0; off >>= 1) {
            if (tid < off) { sS[tid] += sS[tid + off]; sS2[tid] += sS2[tid + off]; }
            __syncthreads();
        }
        if (tid == 0) {
            float m = sS[0] * invCnt;
            float v = sS2[0] * invCnt - m * m;
            sMean = m;
            sRstd = rsqrtf(v + 1e-5f);
        }
        __syncthreads();
    }

    unsigned long long acc[4][NL];
#pragma unroll
    for (int mp = 0; mp < 4; mp++)
#pragma unroll
        for (int j = 0; j < NL; j++) acc[mp][j] = 0ull;

    int buf = 0;
    for (int kc = 0; kc < NCH; kc++) {
        if (kc + 1 < NCH) {
            load_chunk(kc + 1, buf ^ 1);
            asm volatile("cp.async.wait_group 1;");
        } else {
            asm volatile("cp.async.wait_group 0;");
        }
        __syncthreads();
        const float* wr = sW + buf * 64 * 128 + (tm << 3);
        const float* xr = sX + buf * 64 * LT + tl * NL;
#pragma unroll 4
        for (int kk = 0; kk < 64; kk++) {
            ulonglong2 wp01 = *(const ulonglong2*)(wr + (kk << 7));
            ulonglong2 wp23 = *(const ulonglong2*)(wr + (kk << 7) + 4);
            unsigned long long wp[4] = {wp01.x, wp01.y, wp23.x, wp23.y};
            float xv[NL];
            *(float4*)xv = *(const float4*)(xr + kk * LT);
            if (NL == 8) *(float4*)(xv + 4) = *(const float4*)(xr + kk * LT + 4);
            unsigned long long xp[NL];
#pragma unroll
            for (int j = 0; j < NL; j++) {
                uint32_t u = __float_as_uint(xv[j]);
                asm("mov.b64 %0, {%1, %1};" : "=l"(xp[j]) : "r"(u));
            }
#pragma unroll
            for (int mp = 0; mp < 4; mp++)
#pragma unroll
                for (int j = 0; j < NL; j++)
                    asm("fma.rn.f32x2 %0, %1, %2, %0;"
                        : "+l"(acc[mp][j]) : "l"(wp[mp]), "l"(xp[j]));
        }
        __syncthreads();
        buf ^= 1;
    }

    float mean = 0.f, rstd = 1.f;
    if (STATS) { mean = sMean; rstd = sRstd; }
    const int lbase = l0 + tl * NL;
#pragma unroll
    for (int mp = 0; mp < 4; mp++) {
#pragma unroll
        for (int half = 0; half < 2; half++) {
            int o = m0 + (tm << 3) + 2 * mp + half;
            float bias = 0.f;
            if (STATS) bias = ba[o] - mean * rstd * bb[o];
            float* yp = Y + ((size_t)b * Mtotal + o) * ystride + lbase;
            float vals[NL];
#pragma unroll
            for (int j = 0; j < NL; j++) {
                unsigned long long u = acc[mp][j];
                uint32_t w = half ? (uint32_t)(u >> 32) : (uint32_t)u;
                float v = __uint_as_float(w);
                if (STATS) v = fmaf(rstd, v, bias);
                vals[j] = v;
            }
#pragma unroll
            for (int g4 = 0; g4 < NL / 4; g4++) {
                if (MASK && (lbase + (g4 << 2)) >= LQ) continue;
                float4 v4 = *(float4*)(vals + (g4 << 2));
                if (RES) {
                    float4 r = *(const float4*)(yp + (g4 << 2));
                    v4.x += r.x; v4.y += r.y; v4.z += r.z; v4.w += r.w;
                }
                if (SIG) {
                    v4.x = 1.f / (1.f + expf(-v4.x));
                    v4.y = 1.f / (1.f + expf(-v4.y));
                    v4.z = 1.f / (1.f + expf(-v4.z));
                    v4.w = 1.f / (1.f + expf(-v4.w));
                }
                *(float4*)(yp + (g4 << 2)) = v4;
            }
        }
    }
}

// ---------------- launch ----------------
extern "C" void kernel_launch(void* const* d_in, const int* in_sizes, int n_in,
                              void* d_out, int out_size) {
    const float* x      = (const float*)d_in[0];
    const float* gn_g   = (const float*)d_in[1];
    const float* gn_b   = (const float*)d_in[2];
    const float* w_comp = (const float*)d_in[3];
    const float* dw_w   = (const float*)d_in[4];
    const float* pr_a   = (const float*)d_in[5];
    const float* tn_g   = (const float*)d_in[6];
    const float* tn_b   = (const float*)d_in[7];
    const float* pw_w   = (const float*)d_in[8];
    const float* w_exp  = (const float*)d_in[9];
    float* out = (float*)d_out;

    float *p_buf0, *p_buf1, *p_wgT, *p_wb, *p_wgs, *p_pwgT, *p_pwb, *p_pwgs,
          *p_wexpT, *p_part;
    cudaGetSymbolAddress((void**)&p_buf0,  g_buf0);
    cudaGetSymbolAddress((void**)&p_buf1,  g_buf1);
    cudaGetSymbolAddress((void**)&p_wgT,   g_wgT);
    cudaGetSymbolAddress((void**)&p_wb,    g_wb);
    cudaGetSymbolAddress((void**)&p_wgs,   g_wgs);
    cudaGetSymbolAddress((void**)&p_pwgT,  g_pwgT);
    cudaGetSymbolAddress((void**)&p_pwb,   g_pwb);
    cudaGetSymbolAddress((void**)&p_pwgs,  g_pwgs);
    cudaGetSymbolAddress((void**)&p_wexpT, g_wexpT);
    cudaGetSymbolAddress((void**)&p_part,  g_part);

    const int SM64  = (2 * 64 * 128 + 2 * 64 * 64) * 4;   // 96 KB
    const int SM128 = (2 * 64 * 128 + 2 * 64 * 128) * 4;  // 128 KB
    cudaFuncSetAttribute(gemm2_kernel<512, 64, true, false, false, false>,
                         cudaFuncAttributeMaxDynamicSharedMemorySize, SM64);
    cudaFuncSetAttribute(gemm2_kernel<128, 128, true, true, false, false>,
                         cudaFuncAttributeMaxDynamicSharedMemorySize, SM128);
    cudaFuncSetAttribute(gemm2_kernel<128, 128, false, false, true, true>,
                         cudaFuncAttributeMaxDynamicSharedMemorySize, SM128);

    // ---- weight prep (tiny) ----
    transpose_wg_kernel<<<(NC * BC + 255) / 256, 256>>>(w_comp, gn_g, p_wgT);
    sums_wg_kernel<<<1, 128>>>(w_comp, gn_g, gn_b, p_wb, p_wgs);
    transpose_pw_kernel<<<dim3((BC * BC + 255) / 256, NBLK_), 256>>>(pw_w, tn_g, p_pwgT);
    sums_pw_kernel<<<NBLK_, 128>>>(pw_w, tn_g, tn_b, p_pwb, p_pwgs);
    transpose_wexp_kernel<<<(BC * 1024 + 255) / 256, 256>>>(w_exp, p_wexpT);

    // ---- outer GroupNorm stats on x ----
    rowstats_kernel<<<dim3(NC, 4), 256>>>(x, p_part);

    // ---- GN-fused compression GEMM: x[4,512,8000] -> buf0[4,128,8064-padded] ----
    gemm2_kernel<512, 64, true, false, false, false><<<dim3(125, 1, 4), 256, SM64>>>(
        p_wgT, x, LQ, p_buf0, LP, BC, p_wb, p_wgs, p_part, NC,
        1.f / ((float)NC * (float)LQ));

    // ---- 24 TCN blocks ----
    for (int i = 0; i < NBLK_; i++) {
        int d = 1 << (i & 7);
        dwconv_kernel<<<dim3(BC, 4), 256>>>(p_buf0, dw_w + i * BC * 3,
                                            pr_a + i * BC, d, p_buf1, p_part);
        gemm2_kernel<128, 128, true, true, false, false><<<dim3(63, 1, 4), 256, SM128>>>(
            p_pwgT + (size_t)i * BC * BC, p_buf1, LP, p_buf0, LP, BC,
            p_pwb + i * BC, p_pwgs + i * BC, p_part, BC,
            1.f / ((float)BC * (float)LQ));
    }

    // ---- expansion GEMM + sigmoid: buf0 -> out[4,1024,8000] (masked stores) ----
    gemm2_kernel<128, 128, false, false, true, true><<<dim3(63, 8, 4), 256, SM128>>>(
        p_wexpT, p_buf0, LP, out, LQ, 1024, nullptr, nullptr, nullptr, 0, 0.f);
}

// round 9
// speedup vs baseline: 1.9708x; 1.0670x over previous
#include <cuda_runtime.h>
#include <cuda_bf16.h>
#include <math.h>
#include <stdint.h>

#define LQ 8000
#define LPAD 8192
#define NTL 63

// ---------------- device scratch (no allocation allowed) ----------------
__device__ float g_out[4 * LPAD * 128];                 // activation [b][l][c]
__device__ __nv_bfloat16 g_xhi[4 * NTL * 4 * 16384];    // xT split tiles
__device__ __nv_bfloat16 g_xlo[4 * NTL * 4 * 16384];
__device__ __nv_bfloat16 g_hhi[4 * NTL * 16384];        // conv-out / split tiles
__device__ __nv_bfloat16 g_hlo[4 * NTL * 16384];
__device__ __nv_bfloat16 g_cwh[4 * 16384];              // compression W tiles
__device__ __nv_bfloat16 g_cwl[4 * 16384];
__device__ __nv_bfloat16 g_pwh[24 * 16384];             // pointwise W tiles
__device__ __nv_bfloat16 g_pwl[24 * 16384];
__device__ __nv_bfloat16 g_ewh[8 * 16384];              // expansion W tiles
__device__ __nv_bfloat16 g_ewl[8 * 16384];
__device__ float g_wb[128], g_wgs[128];
__device__ float g_pwb[24 * 128], g_pwgs[24 * 128];
__device__ float g_partx[4 * 512 * 2];
__device__ float g_partc[4 * NTL * 2];

// ---------------- helpers ----------------
// swizzled half-index inside a [128 rows][128 bf16 cols] tile (rows of 256B,
// 16B chunks XOR-swizzled by row&7 -> conflict-free ldmatrix)
__device__ __forceinline__ int swz_half(int row, int c) {
    return row * 128 + ((((c >> 3) ^ (row & 7)) << 3) | (c & 7));
}
__device__ __forceinline__ uint32_t smem_u32(const void* p) {
    uint32_t a;
    asm("{ .reg .u64 t; cvta.to.shared.u64 t, %1; cvt.u32.u64 %0, t; }" : "=r"(a) : "l"(p));
    return a;
}
__device__ __forceinline__ void cp16(uint32_t dst, const void* src) {
    asm volatile("cp.async.cg.shared.global [%0], [%1], 16;" :: "r"(dst), "l"(src));
}
__device__ __forceinline__ void ldsm4(uint32_t* r, uint32_t addr) {
    asm volatile("ldmatrix.sync.aligned.m8n8.x4.shared.b16 {%0,%1,%2,%3}, [%4];"
                 : "=r"(r[0]), "=r"(r[1]), "=r"(r[2]), "=r"(r[3]) : "r"(addr));
}
__device__ __forceinline__ void mma16816(float* c, const uint32_t* a,
                                         uint32_t b0, uint32_t b1) {
    asm volatile(
        "mma.sync.aligned.m16n8k16.row.col.f32.bf16.bf16.f32 "
        "{%0,%1,%2,%3}, {%4,%5,%6,%7}, {%8,%9}, {%0,%1,%2,%3};"
        : "+f"(c[0]), "+f"(c[1]), "+f"(c[2]), "+f"(c[3])
        : "r"(a[0]), "r"(a[1]), "r"(a[2]), "r"(a[3]), "r"(b0), "r"(b1));
}

// ---------------- weight prep ----------------
__global__ void comp_img_kernel(const float* __restrict__ w, const float* __restrict__ g,
                                __nv_bfloat16* __restrict__ ih, __nv_bfloat16* __restrict__ il) {
    int idx = blockIdx.x * 256 + threadIdx.x;      // 65536 = 512n x 128o
    int n = idx >> 7, o = idx & 127;
    float wv = w[o * 512 + n] * g[n];
    __nv_bfloat16 hi = __float2bfloat16(wv);
    int pos = (n >> 7) * 16384 + swz_half(o, n & 127);
    ih[pos] = hi;
    il[pos] = __float2bfloat16(wv - __bfloat162float(hi));
}
__global__ void sums_wg_kernel(const float* __restrict__ w, const float* __restrict__ g,
                               const float* __restrict__ beta,
                               float* __restrict__ wb, float* __restrict__ wgs) {
    int o = threadIdx.x;
    float sb = 0.f, sg = 0.f;
    for (int n = 0; n < 512; n++) {
        float wv = w[o * 512 + n];
        sb += wv * beta[n];
        sg += wv * g[n];
    }
    wb[o] = sb; wgs[o] = sg;
}
__global__ void pw_img_kernel(const float* __restrict__ pw, const float* __restrict__ tg,
                              __nv_bfloat16* __restrict__ ih, __nv_bfloat16* __restrict__ il) {
    int i = blockIdx.x;
    for (int it = 0; it < 64; it++) {
        int idx = threadIdx.x + (it << 8);
        int o = idx >> 7, c = idx & 127;
        float wv = pw[(size_t)i * 16384 + o * 128 + c] * tg[i * 128 + c];
        __nv_bfloat16 hi = __float2bfloat16(wv);
        int pos = i * 16384 + swz_half(o, c);
        ih[pos] = hi;
        il[pos] = __float2bfloat16(wv - __bfloat162float(hi));
    }
}
__global__ void sums_pw_kernel(const float* __restrict__ pw, const float* __restrict__ tg,
                               const float* __restrict__ tb,
                               float* __restrict__ pwb, float* __restrict__ pwgs) {
    int i = blockIdx.x, o = threadIdx.x;
    float sb = 0.f, sg = 0.f;
    for (int c = 0; c < 128; c++) {
        float wv = pw[(size_t)(i * 128 + o) * 128 + c];
        sb += wv * tb[i * 128 + c];
        sg += wv * tg[i * 128 + c];
    }
    pwb[i * 128 + o] = sb; pwgs[i * 128 + o] = sg;
}
__global__ void exp_img_kernel(const float* __restrict__ we,
                               __nv_bfloat16* __restrict__ ih, __nv_bfloat16* __restrict__ il) {
    int t = blockIdx.x;
    for (int it = 0; it < 64; it++) {
        int idx = threadIdx.x + (it << 8);
        int o = idx >> 7, c = idx & 127;
        float wv = we[(size_t)((t << 7) + o) * 128 + c];
        __nv_bfloat16 hi = __float2bfloat16(wv);
        int pos = t * 16384 + swz_half(o, c);
        ih[pos] = hi;
        il[pos] = __float2bfloat16(wv - __bfloat162float(hi));
    }
}

// ---------------- per-row stats of x ----------------
__global__ void rowstats_kernel(const float* __restrict__ src, float* __restrict__ part) {
    int c = blockIdx.x, b = blockIdx.y;
    const float4* row = (const float4*)(src + ((size_t)b * 512 + c) * LQ);
    float s = 0.f, ss = 0.f;
    for (int i = threadIdx.x; i < LQ / 4; i += 256) {
        float4 v = row[i];
        s += v.x + v.y + v.z + v.w;
        ss += v.x * v.x + v.y * v.y + v.z * v.z + v.w * v.w;
    }
    __shared__ float rs[256], rss[256];
    rs[threadIdx.x] = s; rss[threadIdx.x] = ss;
    __syncthreads();
    for (int off = 128; off > 0; off >>= 1) {
        if ((int)threadIdx.x < off) {
            rs[threadIdx.x] += rs[threadIdx.x + off];
            rss[threadIdx.x] += rss[threadIdx.x + off];
        }
        __syncthreads();
    }
    if (threadIdx.x == 0) {
        part[(b * 512 + c) * 2 + 0] = rs[0];
        part[(b * 512 + c) * 2 + 1] = rss[0];
    }
}

// ---------------- transpose+split x into swizzled bf16 tiles ----------------
__global__ void __launch_bounds__(256) xsplit_kernel(
    const float* __restrict__ x,
    __nv_bfloat16* __restrict__ Xhi, __nv_bfloat16* __restrict__ Xlo) {
    extern __shared__ char sm[];
    __nv_bfloat16* th = (__nv_bfloat16*)sm;
    __nv_bfloat16* tl = (__nv_bfloat16*)(sm + 32768);
    int t = blockIdx.x, b = blockIdx.y, tid = threadIdx.x;
    int ll = tid & 127, nh = tid >> 7;
    for (int kc = 0; kc < 4; kc++) {
        for (int i = 0; i < 64; i++) {
            int n = (i << 1) + nh;
            int l = t * 128 + ll;
            float v = (l < LQ) ? x[((size_t)(b * 512 + kc * 128 + n)) * LQ + l] : 0.f;
            __nv_bfloat16 hi = __float2bfloat16(v);
            int pos = swz_half(ll, n);
            th[pos] = hi;
            tl[pos] = __float2bfloat16(v - __bfloat162float(hi));
        }
        __syncthreads();
        float4* gh = (float4*)(Xhi + ((size_t)((b * NTL + t) * 4 + kc)) * 16384);
        float4* gl = (float4*)(Xlo + ((size_t)((b * NTL + t) * 4 + kc)) * 16384);
        for (int i = tid; i < 2048; i += 256) { gh[i] = ((float4*)th)[i]; gl[i] = ((float4*)tl)[i]; }
        __syncthreads();
    }
}

// depthwise conv + PReLU + split + masked stats; CONVMODE=false -> pure split
template <bool CONVMODE>
__global__ void __launch_bounds__(256) conv_kernel(
    const float* __restrict__ X, const float* __restrict__ dw3,
    const float* __restrict__ pra, int d,
    __nv_bfloat16* __restrict__ Hhi, __nv_bfloat16* __restrict__ Hlo,
    float* __restrict__ part) {
    extern __shared__ char sm[];
    __nv_bfloat16* th = (__nv_bfloat16*)sm;
    __nv_bfloat16* tl = (__nv_bfloat16*)(sm + 32768);
    float* red = (float*)(sm + 65536);
    float* red2 = red + 256;
    int t = blockIdx.x, b = blockIdx.y, tid = threadIdx.x;
    int c = tid & 127, lh = tid >> 7;
    float w0 = 0.f, w1 = 0.f, w2 = 0.f, a = 0.f;
    if (CONVMODE) { w0 = dw3[c * 3]; w1 = dw3[c * 3 + 1]; w2 = dw3[c * 3 + 2]; a = pra[c]; }
    const float* Xb = X + ((size_t)b * LPAD) * 128;
    int d2 = d << 1;
    float s = 0.f, ss = 0.f;
#pragma unroll 4
    for (int i = 0; i < 64; i++) {
        int ll = (i << 1) + lh;
        int l = t * 128 + ll;
        size_t idx = ((size_t)l << 7) + c;
        float v;
        if (CONVMODE) {
            v = w2 * Xb[idx];
            if (l >= d)  v += w1 * Xb[idx - ((size_t)d << 7)];
            if (l >= d2) v += w0 * Xb[idx - ((size_t)d2 << 7)];
            v = v > 0.f ? v : a * v;
            if (l < LQ) { s += v; ss += v * v; }
        } else {
            v = Xb[idx];
        }
        __nv_bfloat16 hi = __float2bfloat16(v);
        int pos = swz_half(ll, c);
        th[pos] = hi;
        tl[pos] = __float2bfloat16(v - __bfloat162float(hi));
    }
    if (CONVMODE) {
        red[tid] = s; red2[tid] = ss;
        __syncthreads();
        for (int off = 128; off > 0; off >>= 1) {
            if (tid < off) { red[tid] += red[tid + off]; red2[tid] += red2[tid + off]; }
            __syncthreads();
        }
        if (tid == 0) {
            part[(b * NTL + t) * 2 + 0] = red[0];
            part[(b * NTL + t) * 2 + 1] = red2[0];
        }
    } else {
        __syncthreads();
    }
    float4* gh = (float4*)(Hhi + ((size_t)(b * NTL + t)) * 16384);
    float4* gl = (float4*)(Hlo + ((size_t)(b * NTL + t)) * 16384);
    for (int i = tid; i < 2048; i += 256) { gh[i] = ((float4*)th)[i]; gl[i] = ((float4*)tl)[i]; }
}

// ---------------- tensor-core GEMM: D[l][o] = sum_c A[l][c] * W[o][c] ----------------
// mma.sync m16n8k16 bf16, 3-term split (AhWh + AhWl + AlWh), fp32 accum.
// 256 threads = 8 warps (4 m x 2 n). CTA tile: 128 l x 128 o, K = KCH*128.
template <int KCH, bool STATS, bool RES, bool SIG>
__global__ void __launch_bounds__(256) gemm_mma(
    const __nv_bfloat16* __restrict__ Ahi, const __nv_bfloat16* __restrict__ Alo,
    const __nv_bfloat16* __restrict__ Whi, const __nv_bfloat16* __restrict__ Wlo,
    float* __restrict__ Y,
    const float* __restrict__ ba, const float* __restrict__ bb,
    const float* __restrict__ part, int npart, float invCnt) {
    extern __shared__ char smch[];
    float* ctrl = (float*)smch;            // [0..7] scalars, [64..191] bias[o]
    char* tiles = smch + 1024;
    const uint32_t sAh = smem_u32(tiles);
    const uint32_t sAl = sAh + 32768;
    const uint32_t sWh = sAl + 32768;
    const uint32_t sWl = sWh + 32768;

    const int tid = threadIdx.x;
    const int lt = blockIdx.x, ot = blockIdx.y, b = blockIdx.z;
    const int wid = tid >> 5, lane = tid & 31;
    const int wm = wid & 3, wn = wid >> 2;     // 4 m-warps x 2 n-warps
    const int l0w = wm << 5, o0w = wn << 6;
    const int lrow = (lane & 7) + ((lane >> 3) & 1) * 8;   // ldmatrix lane row offset
    const int lcol = (lane >> 4) * 8;                      // ldmatrix lane col offset

    // kick off first chunk copy immediately
    const size_t tA = ((size_t)(b * NTL + lt)) * KCH * 16384;
    auto load_chunk = [&](int kc) {
        const char* pah = (const char*)(Ahi + tA + (size_t)kc * 16384);
        const char* pal = (const char*)(Alo + tA + (size_t)kc * 16384);
        const char* pwh = (const char*)(Whi + (size_t)(ot * KCH + kc) * 16384);
        const char* pwl = (const char*)(Wlo + (size_t)(ot * KCH + kc) * 16384);
#pragma unroll
        for (int it = 0; it < 8; it++) {
            int o4 = (tid + (it << 8)) << 4;
            cp16(sAh + o4, pah + o4);
            cp16(sAl + o4, pal + o4);
            cp16(sWh + o4, pwh + o4);
            cp16(sWl + o4, pwl + o4);
        }
        asm volatile("cp.async.commit_group;");
    };
    load_chunk(0);

    if (STATS) {   // inline deterministic finalize + bias table (overlaps cp.async)
        __shared__ float s1[256], s2[256];
        float s = 0.f, ss = 0.f;
        for (int c = tid; c < npart; c += 256) {
            s += part[(b * npart + c) * 2];
            ss += part[(b * npart + c) * 2 + 1];
        }
        s1[tid] = s; s2[tid] = ss;
        __syncthreads();
        for (int off = 128; off > 0; off >>= 1) {
            if (tid < off) { s1[tid] += s1[tid + off]; s2[tid] += s2[tid + off]; }
            __syncthreads();
        }
        if (tid == 0) {
            float m = s1[0] * invCnt;
            float v = s2[0] * invCnt - m * m;
            ctrl[4] = m;
            ctrl[5] = rsqrtf(v + 1e-5f);
        }
        __syncthreads();
        if (tid < 128) {
            float m = ctrl[4], r = ctrl[5];
            ctrl[64 + tid] = ba[tid] - m * r * bb[tid];
        }
    }

    float acc[2][8][4];
#pragma unroll
    for (int i = 0; i < 2; i++)
#pragma unroll
        for (int j = 0; j < 8; j++)
#pragma unroll
            for (int q = 0; q < 4; q++) acc[i][j][q] = 0.f;

    for (int kc = 0; kc < KCH; kc++) {
        asm volatile("cp.async.wait_group 0;");
        __syncthreads();
#pragma unroll
        for (int ks = 0; ks < 8; ks++) {
            const int k0 = ks << 4;
            uint32_t ah[2][4], al[2][4];
#pragma unroll
            for (int i = 0; i < 2; i++) {
                int row = l0w + (i << 4) + lrow;
                int c = k0 + lcol;
                uint32_t off = row * 256 + ((((c >> 3) ^ (row & 7))) << 4);
                ldsm4(ah[i], sAh + off);
                ldsm4(al[i], sAl + off);
            }
            uint32_t bh[4][4], bl[4][4];
#pragma unroll
            for (int j4 = 0; j4 < 4; j4++) {
                int row = o0w + (j4 << 4) + lrow;
                int c = k0 + lcol;
                uint32_t off = row * 256 + ((((c >> 3) ^ (row & 7))) << 4);
                ldsm4(bh[j4], sWh + off);
                ldsm4(bl[j4], sWl + off);
            }
#pragma unroll
            for (int i = 0; i < 2; i++)
#pragma unroll
                for (int j = 0; j < 8; j++) {
                    uint32_t b0h = bh[j >> 1][j & 1], b1h = bh[j >> 1][(j & 1) + 2];
                    uint32_t b0l = bl[j >> 1][j & 1], b1l = bl[j >> 1][(j & 1) + 2];
                    mma16816(acc[i][j], ah[i], b0h, b1h);
                    mma16816(acc[i][j], ah[i], b0l, b1l);
                    mma16816(acc[i][j], al[i], b0h, b1h);
                }
        }
        __syncthreads();
        if (kc + 1 < KCH) load_chunk(kc + 1);
    }

    // ---------------- epilogue ----------------
    const float rstd = STATS ? ctrl[5] : 1.f;
    const float* sbias = ctrl + 64;
    if (!SIG) {
        // write [b][l][o] with GN scale/bias (+ residual)
#pragma unroll
        for (int i = 0; i < 2; i++) {
            int lb = lt * 128 + l0w + (i << 4) + (lane >> 2);
#pragma unroll
            for (int j = 0; j < 8; j++) {
                int o = o0w + (j << 3) + ((lane & 3) << 1);
                float b0 = STATS ? sbias[o] : 0.f;
                float b1 = STATS ? sbias[o + 1] : 0.f;
                float* p0 = Y + (((size_t)b * LPAD + lb) << 7) + o;
                float* p1 = p0 + (8 << 7);
                float2 v0 = make_float2(fmaf(rstd, acc[i][j][0], b0),
                                        fmaf(rstd, acc[i][j][1], b1));
                float2 v1 = make_float2(fmaf(rstd, acc[i][j][2], b0),
                                        fmaf(rstd, acc[i][j][3], b1));
                if (RES) {
                    float2 r0 = *(const float2*)p0;
                    float2 r1 = *(const float2*)p1;
                    v0.x += r0.x; v0.y += r0.y;
                    v1.x += r1.x; v1.y += r1.y;
                }
                *(float2*)p0 = v0;
                *(float2*)p1 = v1;
            }
        }
    } else {
        // sigmoid + transpose through smem (reuse tile area), write [b][o][l]
        float* stg = (float*)tiles;     // [128 o][132]
        __syncthreads();
#pragma unroll
        for (int i = 0; i < 2; i++) {
            int lloc = l0w + (i << 4) + (lane >> 2);
#pragma unroll
            for (int j = 0; j < 8; j++) {
                int o = o0w + (j << 3) + ((lane & 3) << 1);
                stg[o * 132 + lloc]           = 1.f / (1.f + __expf(-acc[i][j][0]));
                stg[(o + 1) * 132 + lloc]     = 1.f / (1.f + __expf(-acc[i][j][1]));
                stg[o * 132 + lloc + 8]       = 1.f / (1.f + __expf(-acc[i][j][2]));
                stg[(o + 1) * 132 + lloc + 8] = 1.f / (1.f + __expf(-acc[i][j][3]));
            }
        }
        __syncthreads();
        int l0 = lt * 128;
        int o = tid >> 1, half = tid & 1;
        float* yb = Y + ((size_t)(b * 1024 + (ot << 7) + o)) * LQ + l0;
#pragma unroll
        for (int g = 0; g < 16; g++) {
            int idx = (half << 6) + (g << 2);
            if (l0 + idx < LQ) {
                float4 v = *(float4*)(stg + o * 132 + idx);
                *(float4*)(yb + idx) = v;
            }
        }
    }
}

// ---------------- launch ----------------
extern "C" void kernel_launch(void* const* d_in, const int* in_sizes, int n_in,
                              void* d_out, int out_size) {
    const float* x      = (const float*)d_in[0];
    const float* gn_g   = (const float*)d_in[1];
    const float* gn_b   = (const float*)d_in[2];
    const float* w_comp = (const float*)d_in[3];
    const float* dw_w   = (const float*)d_in[4];
    const float* pr_a   = (const float*)d_in[5];
    const float* tn_g   = (const float*)d_in[6];
    const float* tn_b   = (const float*)d_in[7];
    const float* pw_w   = (const float*)d_in[8];
    const float* w_exp  = (const float*)d_in[9];
    float* out = (float*)d_out;

    float *p_out, *p_wb, *p_wgs, *p_pwb, *p_pwgs, *p_partx, *p_partc;
    __nv_bfloat16 *p_xhi, *p_xlo, *p_hhi, *p_hlo, *p_cwh, *p_cwl, *p_pwh, *p_pwl, *p_ewh, *p_ewl;
    cudaGetSymbolAddress((void**)&p_out, g_out);
    cudaGetSymbolAddress((void**)&p_xhi, g_xhi);  cudaGetSymbolAddress((void**)&p_xlo, g_xlo);
    cudaGetSymbolAddress((void**)&p_hhi, g_hhi);  cudaGetSymbolAddress((void**)&p_hlo, g_hlo);
    cudaGetSymbolAddress((void**)&p_cwh, g_cwh);  cudaGetSymbolAddress((void**)&p_cwl, g_cwl);
    cudaGetSymbolAddress((void**)&p_pwh, g_pwh);  cudaGetSymbolAddress((void**)&p_pwl, g_pwl);
    cudaGetSymbolAddress((void**)&p_ewh, g_ewh);  cudaGetSymbolAddress((void**)&p_ewl, g_ewl);
    cudaGetSymbolAddress((void**)&p_wb, g_wb);    cudaGetSymbolAddress((void**)&p_wgs, g_wgs);
    cudaGetSymbolAddress((void**)&p_pwb, g_pwb);  cudaGetSymbolAddress((void**)&p_pwgs, g_pwgs);
    cudaGetSymbolAddress((void**)&p_partx, g_partx);
    cudaGetSymbolAddress((void**)&p_partc, g_partc);

    const int SMG = 1024 + 4 * 32768;   // 132 KB
    cudaFuncSetAttribute(gemm_mma<4, true, false, false>,
                         cudaFuncAttributeMaxDynamicSharedMemorySize, SMG);
    cudaFuncSetAttribute(gemm_mma<1, true, true, false>,
                         cudaFuncAttributeMaxDynamicSharedMemorySize, SMG);
    cudaFuncSetAttribute(gemm_mma<1, false, false, true>,
                         cudaFuncAttributeMaxDynamicSharedMemorySize, SMG);
    cudaFuncSetAttribute(conv_kernel<true>, cudaFuncAttributeMaxDynamicSharedMemorySize, 67584);
    cudaFuncSetAttribute(conv_kernel<false>, cudaFuncAttributeMaxDynamicSharedMemorySize, 67584);
    cudaFuncSetAttribute(xsplit_kernel, cudaFuncAttributeMaxDynamicSharedMemorySize, 65536);

    // weight prep
    comp_img_kernel<<<256, 256>>>(w_comp, gn_g, p_cwh, p_cwl);
    sums_wg_kernel<<<1, 128>>>(w_comp, gn_g, gn_b, p_wb, p_wgs);
    pw_img_kernel<<<24, 256>>>(pw_w, tn_g, p_pwh, p_pwl);
    sums_pw_kernel<<<24, 128>>>(pw_w, tn_g, tn_b, p_pwb, p_pwgs);
    exp_img_kernel<<<8, 256>>>(w_exp, p_ewh, p_ewl);

    // outer GN stats + x transpose/split
    rowstats_kernel<<<dim3(512, 4), 256>>>(x, p_partx);
    xsplit_kernel<<<dim3(NTL, 4), 256, 65536>>>(x, p_xhi, p_xlo);

    // compression: xT @ Wc -> g_out [b][l][128]
    gemm_mma<4, true, false, false><<<dim3(NTL, 1, 4), 256, SMG>>>(
        p_xhi, p_xlo, p_cwh, p_cwl, p_out, p_wb, p_wgs, p_partx, 512,
        1.f / (512.f * (float)LQ));

    // 24 TCN blocks
    for (int i = 0; i < 24; i++) {
        int d = 1 << (i & 7);
        conv_kernel<true><<<dim3(NTL, 4), 256, 67584>>>(p_out, dw_w + i * 128 * 3,
                                                        pr_a + i * 128, d, p_hhi, p_hlo, p_partc);
        gemm_mma<1, true, true, false><<<dim3(NTL, 1, 4), 256, SMG>>>(
            p_hhi, p_hlo, p_pwh + (size_t)i * 16384, p_pwl + (size_t)i * 16384,
            p_out, p_pwb + i * 128, p_pwgs + i * 128, p_partc, NTL,
            1.f / (128.f * (float)LQ));
    }

    // split final activation, then expansion + sigmoid -> d_out [b][1024][8000]
    conv_kernel<false><<<dim3(NTL, 4), 256, 67584>>>(p_out, nullptr, nullptr, 1,
                                                     p_hhi, p_hlo, p_partc);
    gemm_mma<1, false, false, true><<<dim3(NTL, 8, 4), 256, SMG>>>(
        p_hhi, p_hlo, p_ewh, p_ewl, out, nullptr, nullptr, nullptr, 0, 0.f);
}